// round 16
// baseline (speedup 1.0000x reference)
#include <cuda_runtime.h>

// Problem constants
#define NPTS 4096
#define DIMK 256
#define NEPS 4
#define NWRD 128              // 4096 bits / 32 per row
#define NN   (NPTS*NPTS)      // 16777216

// Output layout (float32, concatenated in reference return order)
#define LOSS_OFF 0u
#define VM_OFF   4096u
#define A_OFF    20480u                      // 4096 + 4*4096
#define TRI_OFF  (20480u + 67108864u)        // + E*N*N

// ---------------- device scratch (globals: allocation-free rule) ----------
__device__ float          g_d[NN];                 // 67 MB distance matrix
__device__ unsigned       g_abits[NEPS][NPTS*NWRD];// 8 MB packed adjacency
__device__ unsigned       g_cbits[NEPS][NPTS*NWRD];// 8 MB compacted adjacency
__device__ unsigned char  g_as8[(size_t)NEPS*NN];  // 67 MB s8 0/1 adjacency
__device__ float          g_tric[(size_t)NEPS*NN]; // 268 MB compacted counts
__device__ float          g_sq[NPTS];
__device__ unsigned char  g_vmb[NPTS];             // 4 mask bits per point
__device__ unsigned char  g_lvl[NPTS];             // first alive level (4=dead)
__device__ int            g_rank[NEPS][NPTS];      // rank among alive, -1 dead
__device__ int            g_plist[NEPS][NPTS];     // rank -> point index
__device__ int            g_m[NEPS];               // alive count
__device__ unsigned       g_hist[NEPS][2048];      // radix histograms (L or e)
__device__ unsigned       g_pref[NEPS];
__device__ unsigned       g_k[NEPS];
__device__ unsigned       g_thrbits[NEPS];
__device__ int            g_done[NEPS];

// ---------------- Stage 1: losses, vmask, sqnorms, levels -------------------
// Bit-exact XLA row-reduce: warp per row, lane-stride-32 ascending FMA, then
// shfl_down tree (16,8,4,2,1). DO NOT change the arithmetic order.
__global__ void prep_kernel(const float* __restrict__ residue,
                            const float* __restrict__ constraint,
                            const float* __restrict__ eps,
                            float* __restrict__ out) {
    int gw   = (blockIdx.x * blockDim.x + threadIdx.x) >> 5;   // row id
    int lane = threadIdx.x & 31;
    if (gw >= NPTS) return;

    const float* __restrict__ c = constraint + (unsigned)gw * DIMK;
    const float* __restrict__ r = residue    + (unsigned)gw * DIMK;

    float s_sq = 0.f, s_ls = 0.f;
    #pragma unroll
    for (int j = 0; j < 8; j++) {
        float cv = c[lane + 32 * j];
        float rv = r[lane + 32 * j];
        s_sq = __fmaf_rn(cv, cv, s_sq);
        float df = __fadd_rn(rv, -cv);
        s_ls = __fmaf_rn(df, df, s_ls);
    }
    #pragma unroll
    for (int o = 16; o > 0; o >>= 1) {
        s_sq = __fadd_rn(s_sq, __shfl_down_sync(0xffffffffu, s_sq, o));
        s_ls = __fadd_rn(s_ls, __shfl_down_sync(0xffffffffu, s_ls, o));
    }

    if (lane == 0) {
        g_sq[gw] = s_sq;
        float loss = __fsqrt_rn(s_ls);
        out[LOSS_OFF + gw] = loss;
        unsigned char mb = 0;
        #pragma unroll
        for (int e = 0; e < NEPS; e++) {
            bool m = loss <= eps[e];
            mb |= (unsigned char)((m ? 1 : 0) << e);
            out[VM_OFF + (unsigned)e * NPTS + gw] = m ? 1.f : 0.f;
        }
        g_vmb[gw] = mb;
        g_lvl[gw] = (unsigned char)(mb ? (__ffs((int)mb) - 1) : NEPS);
    }
}

// ---------------- Stage 1b: per-eps compaction ranks ------------------------
__global__ void ranks_kernel() {
    int e = threadIdx.x >> 5, lane = threadIdx.x & 31;
    int base = lane * 128;
    int cnt = 0;
    for (int q = 0; q < 128; q++)
        cnt += (g_vmb[base + q] >> e) & 1;
    int incl = cnt;
    #pragma unroll
    for (int o = 1; o < 32; o <<= 1) {
        int v = __shfl_up_sync(0xffffffffu, incl, o);
        if (lane >= o) incl += v;
    }
    int m = __shfl_sync(0xffffffffu, incl, 31);
    int run = incl - cnt;
    for (int q = 0; q < 128; q++) {
        int idx = base + q;
        if ((g_vmb[idx] >> e) & 1) {
            g_rank[e][idx] = run;
            g_plist[e][run] = idx;
            run++;
        } else {
            g_rank[e][idx] = -1;
        }
    }
    if (lane == 0) g_m[e] = m;
}

// ---------------- no-op spacer (launch alignment for ncu) -------------------
__global__ void nop_kernel() {}

// ---------------- Stage 2: pairwise distances (fp32, packed FFMA2) ---------
// Round-11 j-packed config (best measured). Triangular grid; bit-exact
// symmetric mirror via smem-staged transpose. Single accumulator per element,
// k strictly ascending -> bit-exact.
__global__ void __launch_bounds__(256, 2)
dist_kernel(const float* __restrict__ C) {
    int bx = blockIdx.x, by = blockIdx.y;
    if (by > bx) return;

    __shared__ __align__(16) float smem[64 * 129];   // 33 KB union buffer
    float* shI = smem;                  // 16*132 floats
    float* shJ = smem + 16 * 132;       // 16*132 floats
    float* stage = smem;                // 64*129 floats (post-mainloop)

    int i0 = by * 128, j0 = bx * 128;
    int t  = threadIdx.x;
    int tx = t & 15, ty = t >> 4;
    unsigned long long accp[8][4] = {};   // (lo,hi) fp32 pairs, init 0.0f

    for (int k0 = 0; k0 < DIMK; k0 += 16) {
        #pragma unroll
        for (int r = 0; r < 2; r++) {
            int q   = t + r * 256;        // 0..511
            int row = q & 127;
            int kv  = q >> 7;             // 0..3 -> k offset kv*4
            float4 vI = *(const float4*)&C[(i0 + row) * DIMK + k0 + kv * 4];
            float4 vJ = *(const float4*)&C[(j0 + row) * DIMK + k0 + kv * 4];
            shI[(kv * 4 + 0) * 132 + row] = vI.x;
            shI[(kv * 4 + 1) * 132 + row] = vI.y;
            shI[(kv * 4 + 2) * 132 + row] = vI.z;
            shI[(kv * 4 + 3) * 132 + row] = vI.w;
            shJ[(kv * 4 + 0) * 132 + row] = vJ.x;
            shJ[(kv * 4 + 1) * 132 + row] = vJ.y;
            shJ[(kv * 4 + 2) * 132 + row] = vJ.z;
            shJ[(kv * 4 + 3) * 132 + row] = vJ.w;
        }
        __syncthreads();
        #pragma unroll
        for (int kk = 0; kk < 16; kk++) {
            unsigned long long aid[8], bjp[4];
            #pragma unroll
            for (int a = 0; a < 8; a++) {
                unsigned av = __float_as_uint(shI[kk * 132 + ty + 16 * a]);
                asm("mov.b64 %0, {%1, %1};" : "=l"(aid[a]) : "r"(av));
            }
            #pragma unroll
            for (int b = 0; b < 4; b++)
                bjp[b] = *(const unsigned long long*)
                             &shJ[kk * 132 + (tx + 16 * b) * 2];
            #pragma unroll
            for (int a = 0; a < 8; a++)
                #pragma unroll
                for (int b = 0; b < 4; b++)
                    asm("fma.rn.f32x2 %0, %1, %2, %3;"
                        : "=l"(accp[a][b])
                        : "l"(aid[a]), "l"(bjp[b]), "l"(accp[a][b]));
        }
        __syncthreads();
    }

    float sqi[8];
    #pragma unroll
    for (int a = 0; a < 8; a++) sqi[a] = g_sq[i0 + ty + 16 * a];

    #pragma unroll
    for (int h = 0; h < 2; h++) {
        __syncthreads();
        #pragma unroll
        for (int a4 = 0; a4 < 4; a4++) {
            int a  = h * 4 + a4;
            int il = ty + 16 * a;                   // local i row
            int i  = i0 + il;
            #pragma unroll
            for (int b = 0; b < 4; b++) {
                unsigned lo, hi;
                asm("mov.b64 {%0, %1}, %2;"
                    : "=r"(lo), "=r"(hi) : "l"(accp[a][b]));
                int jcl = (tx + 16 * b) * 2;        // local j col (even)
                int jc  = j0 + jcl;
                float accv[2] = {__uint_as_float(lo), __uint_as_float(hi)};
                float v[2];
                #pragma unroll
                for (int hh = 0; hh < 2; hh++) {
                    float t1 = __fadd_rn(sqi[a], g_sq[jc + hh]);
                    float g2 = __fmul_rn(2.0f, accv[hh]);
                    float d2 = __fadd_rn(t1, -g2);
                    v[hh] = __fsqrt_rn(fmaxf(d2, 0.0f));
                    stage[(il - h * 64) * 129 + jcl + hh] = v[hh];
                }
                *(float2*)&g_d[(unsigned)i * NPTS + jc] = make_float2(v[0], v[1]);
            }
        }
        __syncthreads();
        if (bx != by) {
            #pragma unroll
            for (int a2 = 0; a2 < 8; a2++) {
                int jl = ty + 16 * a2;
                #pragma unroll
                for (int b2 = 0; b2 < 4; b2++) {
                    int ic = tx + 16 * b2;          // 0..63
                    g_d[(unsigned)(j0 + jl) * NPTS + i0 + h * 64 + ic] =
                        stage[ic * 129 + jl];
                }
            }
        }
    }
}

// ---------------- Stage 3a: pass-0 histogram, upper triangle, branchless ---
__global__ void hist0_kernel() {
    __shared__ unsigned sh[NEPS * 2048];
    int tid = threadIdx.x;
    for (int q = tid; q < NEPS * 2048; q += 256) sh[q] = 0;
    __syncthreads();

    unsigned lane = (unsigned)(tid & 31);
    const float4* __restrict__ d4 = (const float4*)g_d;
    for (unsigned idx = blockIdx.x * 256u + tid; idx < (unsigned)(NN / 4);
         idx += gridDim.x * 256u) {
        unsigned i  = idx >> 10;
        unsigned j4 = (idx & 1023u) * 4u;
        if (__all_sync(0xffffffffu, j4 + 3u < i)) continue;  // warp-uniform skip
        float4 v = d4[idx];
        uchar4 lj = *(const uchar4*)&g_lvl[j4];
        unsigned li = (unsigned)g_lvl[i];
        float dv[4] = {v.x, v.y, v.z, v.w};
        unsigned lv[4] = {max(li, (unsigned)lj.x), max(li, (unsigned)lj.y),
                          max(li, (unsigned)lj.z), max(li, (unsigned)lj.w)};
        #pragma unroll
        for (int c = 0; c < 4; c++) {
            unsigned j = j4 + (unsigned)c;
            unsigned w = (j > i) ? 2u : ((j == i) ? 1u : 0u);
            bool valid = (w != 0u) && (dv[c] > 0.f) && (lv[c] < (unsigned)NEPS);
            unsigned key = valid
                ? (lv[c] * 2048u + (__float_as_uint(dv[c]) >> 20))
                : (0x80000000u | lane);
            unsigned wc_ = valid ? w : 0u;
            unsigned peers = __match_any_sync(0xffffffffu, key);
            unsigned b0 = __ballot_sync(0xffffffffu, wc_ & 1u);
            unsigned b1 = __ballot_sync(0xffffffffu, wc_ & 2u);
            if (valid && lane == (unsigned)(__ffs(peers) - 1)) {
                unsigned s = __popc(peers & b0) + 2u * __popc(peers & b1);
                atomicAdd(&sh[key], s);
            }
        }
    }
    __syncthreads();
    unsigned* gh = &g_hist[0][0];
    for (int q = tid; q < NEPS * 2048; q += 256) {
        unsigned v = sh[q];
        if (v) atomicAdd(&gh[q], v);
    }
}

// ---------------- Stage 3b: passes 1,2 — upper triangle, direct atomics ----
template<int PASS>
__global__ void hist12_kernel() {
    __shared__ unsigned sh[NEPS * 2048];
    int tid = threadIdx.x;
    for (int q = tid; q < NEPS * 2048; q += 256) sh[q] = 0;
    __syncthreads();

    unsigned pref[NEPS];
    #pragma unroll
    for (int e = 0; e < NEPS; e++) pref[e] = g_pref[e];

    const float4* __restrict__ d4 = (const float4*)g_d;
    for (unsigned idx = blockIdx.x * 256u + tid; idx < (unsigned)(NN / 4);
         idx += gridDim.x * 256u) {
        unsigned i  = idx >> 10;
        unsigned j4 = (idx & 1023u) * 4u;
        if (j4 + 3u < i) continue;               // per-lane ok: atomics only
        float4 v = d4[idx];
        uchar4 lj = *(const uchar4*)&g_lvl[j4];
        unsigned li = (unsigned)g_lvl[i];
        float dv[4] = {v.x, v.y, v.z, v.w};
        unsigned lv[4] = {max(li, (unsigned)lj.x), max(li, (unsigned)lj.y),
                          max(li, (unsigned)lj.z), max(li, (unsigned)lj.w)};
        #pragma unroll
        for (int c = 0; c < 4; c++) {
            unsigned j = j4 + (unsigned)c;
            unsigned w = (j > i) ? 2u : ((j == i) ? 1u : 0u);
            if (w == 0u || !(dv[c] > 0.f) || lv[c] >= (unsigned)NEPS) continue;
            unsigned bits = __float_as_uint(dv[c]);
            unsigned hd   = (PASS == 1) ? (bits >> 20) : (bits >> 9);
            unsigned bin  = (PASS == 1) ? ((bits >> 9) & 2047u) : (bits & 511u);
            #pragma unroll
            for (int e = 0; e < NEPS; e++)
                if (lv[c] <= (unsigned)e && hd == pref[e])
                    atomicAdd(&sh[e * 2048 + bin], w);
        }
    }
    __syncthreads();
    unsigned* gh = &g_hist[0][0];
    for (int q = tid; q < NEPS * 2048; q += 256) {
        unsigned v = sh[q];
        if (v) atomicAdd(&gh[q], v);
    }
}

__global__ void scan_kernel(int pass) {
    __shared__ unsigned shh[NEPS * 2048];
    int tid = threadIdx.x;              // 128 threads: warp e handles eps e
    int e = tid >> 5, lane = tid & 31;

    unsigned* gh = &g_hist[0][0];
    for (int q = tid; q < NEPS * 2048; q += 128) shh[q] = gh[q];
    __syncthreads();

    unsigned chunkSum = 0;
    for (int q = 0; q < 64; q++) {
        unsigned hv;
        if (pass == 0) {
            hv = 0;
            for (int L = 0; L <= e; L++) hv += shh[L * 2048 + lane * 64 + q];
        } else {
            hv = shh[e * 2048 + lane * 64 + q];
        }
        chunkSum += hv;
    }

    unsigned incl = chunkSum;
    #pragma unroll
    for (int o = 1; o < 32; o <<= 1) {
        unsigned v = __shfl_up_sync(0xffffffffu, incl, o);
        if (lane >= o) incl += v;
    }
    unsigned total = __shfl_sync(0xffffffffu, incl, 31);
    unsigned exclusive = incl - chunkSum;

    if (pass == 0 && lane == 0) {
        if (total == 0) {
            g_done[e] = 1;
            g_thrbits[e] = 0x7F800000u;   // +inf
            g_pref[e] = 0xFFFFFFFFu;      // impossible prefix
        } else {
            g_done[e] = 0;
        }
    }

    bool skip = (pass > 0) && (g_done[e] != 0);
    if (!skip && total > 0) {
        unsigned k = (pass == 0) ? ((total - 1u) >> 1) : g_k[e];
        bool mine = (exclusive <= k) && (k < exclusive + chunkSum);
        if (mine) {
            unsigned cum = exclusive, b = 0;
            for (int q = 0; q < 64; q++) {
                unsigned h;
                if (pass == 0) {
                    h = 0;
                    for (int L = 0; L <= e; L++) h += shh[L * 2048 + lane * 64 + q];
                } else {
                    h = shh[e * 2048 + lane * 64 + q];
                }
                if (cum + h > k) { b = (unsigned)(lane * 64 + q); break; }
                cum += h;
            }
            g_k[e] = k - cum;
            if (pass == 0)      g_pref[e] = b;
            else if (pass == 1) g_pref[e] = (g_pref[e] << 11) | b;
            else                g_thrbits[e] = (g_pref[e] << 9) | b;
        }
    }
    __syncthreads();
    for (int q = tid; q < NEPS * 2048; q += 128) gh[q] = 0;
}

// ---------------- Stage 4: packed adjacency bitsets (all eps, 1 d read) ----
__global__ void bits_kernel() {
    unsigned gw   = (blockIdx.x * 256u + threadIdx.x) >> 5;  // warp: (i, wc)
    unsigned lane = threadIdx.x & 31u;
    unsigned i    = gw >> 7;
    unsigned wc   = gw & 127u;
    unsigned j    = (wc << 5) + lane;

    float dv = g_d[i * NPTS + j];
    unsigned both = (unsigned)(g_vmb[i] & g_vmb[j]);
    bool offd = (i != j);

    #pragma unroll
    for (int e = 0; e < NEPS; e++) {
        float thr = __uint_as_float(g_thrbits[e]);
        bool a = (dv <= thr) && ((both >> e) & 1u) && offd;
        unsigned word = __ballot_sync(0xffffffffu, a);
        if (lane == 0) g_abits[e][(i << 7) + wc] = word;
    }
}

// ---------------- Stage 4b: compact adjacency rows by rank ------------------
__global__ void compact_kernel() {
    int i = blockIdx.x, e = blockIdx.y;
    int rk = g_rank[e][i];
    if (rk < 0) return;
    __shared__ unsigned rowbits[128];
    int t = threadIdx.x;                 // 128 threads
    rowbits[t] = g_abits[e][i * 128 + t];
    __syncthreads();
    int m = g_m[e];
    unsigned w = 0;
    int base = t * 32;
    const int* __restrict__ pl = g_plist[e];
    for (int b = 0; b < 32; b++) {
        int idx = base + b;
        if (idx < m) {
            int p = pl[idx];
            w |= ((rowbits[p >> 5] >> (p & 31)) & 1u) << b;
        }
    }
    g_cbits[e][rk * 128 + t] = w;
}

// ---------------- Stage 4c: expand compacted bits -> s8 0/1 matrix ---------
__global__ void as8_kernel() {
    int rb = blockIdx.x, e = blockIdx.y;
    int m = g_m[e];
    int nt = (m + 127) >> 7;
    if (rb >= nt) return;
    int t = threadIdx.x;                 // 256 threads
    unsigned char* __restrict__ A = g_as8 + (size_t)e * NN;
    const unsigned* __restrict__ Ab = g_cbits[e];
    int wtot = nt * 4;                   // words per row actually needed
    for (int rw = t; rw < 128 * wtot; rw += 256) {
        int r = rw / wtot, w = rw % wtot;
        unsigned bits = Ab[(rb * 128 + r) * NWRD + w];
        unsigned char* dst = A + (size_t)(rb * 128 + r) * NPTS + w * 32;
        #define EXP4(bb) ( (((bb) & 1u) ? 0x01u : 0u) | (((bb) & 2u) ? 0x100u : 0u) \
                         | (((bb) & 4u) ? 0x10000u : 0u) | (((bb) & 8u) ? 0x1000000u : 0u) )
        uint4 v0, v1;
        v0.x = EXP4(bits);        v0.y = EXP4(bits >> 4);
        v0.z = EXP4(bits >> 8);   v0.w = EXP4(bits >> 12);
        v1.x = EXP4(bits >> 16);  v1.y = EXP4(bits >> 20);
        v1.z = EXP4(bits >> 24);  v1.w = EXP4(bits >> 28);
        *(uint4*)dst = v0;
        *(uint4*)(dst + 16) = v1;
        #undef EXP4
    }
}

// ---------------- Stage 5: tri = A@A via mma.sync IMMA s8 -------------------
// 128x128 tile per block, 8 warps (2x4), warp tile 64x32, m16n8k32 s8 MMA.
// A symmetric -> D symmetric: upper tiles only + staged-transpose mirror.
// s32 accumulation is exact (counts <= 4096).
__global__ void __launch_bounds__(256)
tric_imma_kernel() {
    int bx = blockIdx.x, by = blockIdx.y, e = blockIdx.z;
    int m = g_m[e];
    int nt = (m + 127) >> 7;
    if (bx >= nt || by > bx) return;
    int i0 = by * 128, j0 = bx * 128;

    // smem: A tile [128][144B] @0, B tile @18432, mask @36864 (2KB)
    __shared__ __align__(16) char sm[38912];
    char* smA = sm;
    char* smB = sm + 18432;
    unsigned* mask = (unsigned*)(sm + 36864);
    float* stage = (float*)sm;           // 64*133 floats, reused post-mainloop

    int t = threadIdx.x;
    int wid = t >> 5, lane = t & 31;
    int wy = wid >> 2, wx = wid & 3;     // warp grid 2 x 4
    int g  = lane >> 2, tig = lane & 3;  // PTX mma group / thread-in-group

    const unsigned char* __restrict__ A8 = g_as8 + (size_t)e * NN;
    int acc[4][4][4] = {};               // [mfrag][nfrag][c0..c3]

    for (int kc = 0; kc < nt; kc++) {
        // fill tiles: 1024 uint4 per tile, 4 per thread
        #pragma unroll
        for (int q = 0; q < 4; q++) {
            int idx = t + q * 256;
            int row = idx >> 3, seg = idx & 7;
            *(uint4*)(smA + row * 144 + seg * 16) =
                *(const uint4*)(A8 + (size_t)(i0 + row) * NPTS + kc * 128 + seg * 16);
            *(uint4*)(smB + row * 144 + seg * 16) =
                *(const uint4*)(A8 + (size_t)(j0 + row) * NPTS + kc * 128 + seg * 16);
        }
        __syncthreads();

        #pragma unroll
        for (int s = 0; s < 4; s++) {            // 4 k32 steps per 128-chunk
            unsigned af[4][4], bf[4][2];
            #pragma unroll
            for (int a = 0; a < 4; a++) {
                const char* p = smA + (wy * 64 + a * 16 + g) * 144 + s * 32 + tig * 4;
                af[a][0] = *(const unsigned*)p;
                af[a][1] = *(const unsigned*)(p + 8 * 144);
                af[a][2] = *(const unsigned*)(p + 16);
                af[a][3] = *(const unsigned*)(p + 8 * 144 + 16);
            }
            #pragma unroll
            for (int b = 0; b < 4; b++) {
                const char* p = smB + (wx * 32 + b * 8 + g) * 144 + s * 32 + tig * 4;
                bf[b][0] = *(const unsigned*)p;
                bf[b][1] = *(const unsigned*)(p + 16);
            }
            #pragma unroll
            for (int a = 0; a < 4; a++)
                #pragma unroll
                for (int b = 0; b < 4; b++)
                    asm volatile(
                        "mma.sync.aligned.m16n8k32.row.col.s32.s8.s8.s32 "
                        "{%0,%1,%2,%3}, {%4,%5,%6,%7}, {%8,%9}, {%0,%1,%2,%3};"
                        : "+r"(acc[a][b][0]), "+r"(acc[a][b][1]),
                          "+r"(acc[a][b][2]), "+r"(acc[a][b][3])
                        : "r"(af[a][0]), "r"(af[a][1]), "r"(af[a][2]), "r"(af[a][3]),
                          "r"(bf[b][0]), "r"(bf[b][1]));
        }
        __syncthreads();
    }

    // A-mask for this tile: rows i0.., words bx*4..+3
    if (t < 128)
        *(uint4*)&mask[t * 4] =
            *(const uint4*)&g_cbits[e][(i0 + t) * NWRD + bx * 4];
    __syncthreads();

    float* __restrict__ trc = g_tric + (size_t)e * NN;

    // normal-orientation masked writes (float2 per nfrag)
    #pragma unroll
    for (int a = 0; a < 4; a++) {
        #pragma unroll
        for (int half = 0; half < 2; half++) {
            int row = wy * 64 + a * 16 + g + half * 8;
            unsigned mw = mask[row * 4 + wx];
            #pragma unroll
            for (int b = 0; b < 4; b++) {
                unsigned sh = (unsigned)(b * 8 + tig * 2);
                float2 v;
                v.x = ((mw >> sh) & 1u)       ? (float)acc[a][b][half * 2]     : 0.f;
                v.y = ((mw >> (sh + 1)) & 1u) ? (float)acc[a][b][half * 2 + 1] : 0.f;
                *(float2*)&trc[(size_t)(i0 + row) * NPTS + j0 + wx * 32 + b * 8 + tig * 2] = v;
            }
        }
    }

    if (bx != by) {   // mirrored tile via staged transpose (64-row halves)
        #pragma unroll
        for (int h = 0; h < 2; h++) {
            __syncthreads();
            if (wy == h) {
                #pragma unroll
                for (int a = 0; a < 4; a++)
                    #pragma unroll
                    for (int half = 0; half < 2; half++) {
                        int rl = a * 16 + g + half * 8;          // 0..63
                        unsigned mw = mask[(h * 64 + rl) * 4 + wx];
                        #pragma unroll
                        for (int b = 0; b < 4; b++) {
                            unsigned sh = (unsigned)(b * 8 + tig * 2);
                            int colb = wx * 32 + b * 8 + tig * 2;
                            stage[rl * 133 + colb] =
                                ((mw >> sh) & 1u) ? (float)acc[a][b][half * 2] : 0.f;
                            stage[rl * 133 + colb + 1] =
                                ((mw >> (sh + 1)) & 1u) ? (float)acc[a][b][half * 2 + 1] : 0.f;
                        }
                    }
            }
            __syncthreads();
            #pragma unroll
            for (int q = 0; q < 8; q++) {
                int idx = q * 256 + t;        // 0..2047 float4 slots
                int jl = idx >> 4;
                int ic = (idx & 15) * 4;
                float4 v;
                v.x = stage[(ic + 0) * 133 + jl];
                v.y = stage[(ic + 1) * 133 + jl];
                v.z = stage[(ic + 2) * 133 + jl];
                v.w = stage[(ic + 3) * 133 + jl];
                *(float4*)&trc[(size_t)(j0 + jl) * NPTS + i0 + h * 64 + ic] = v;
            }
        }
    }
}

// ---------------- Stage 6: expand A and tri to full output ------------------
__global__ void expand_kernel(float* __restrict__ out) {
    int i = blockIdx.x, e = blockIdx.y;
    unsigned baseA = A_OFF   + (unsigned)e * 16777216u + (unsigned)i * 4096u;
    unsigned baseT = TRI_OFF + (unsigned)e * 16777216u + (unsigned)i * 4096u;
    int t = threadIdx.x;                 // 256 threads
    int mi = g_rank[e][i];

    if (mi < 0) {
        float4 z = make_float4(0.f, 0.f, 0.f, 0.f);
        #pragma unroll
        for (int q = t; q < 1024; q += 256) {
            *(float4*)&out[baseA + 4u * q] = z;
            *(float4*)&out[baseT + 4u * q] = z;
        }
        return;
    }

    __shared__ unsigned rowbits[128];
    if (t < 128) rowbits[t] = g_abits[e][i * 128 + t];
    __syncthreads();

    const float* __restrict__ trow = g_tric + (size_t)e * NN + (size_t)mi * 4096u;
    const int4* __restrict__ rnk4 = (const int4*)g_rank[e];

    #pragma unroll
    for (int q = t; q < 1024; q += 256) {
        unsigned nib = rowbits[q >> 3] >> ((q & 7) * 4);   // 4 bits for j=4q..
        float4 a, tr;
        a.x = (nib & 1u) ? 1.f : 0.f;
        a.y = (nib & 2u) ? 1.f : 0.f;
        a.z = (nib & 4u) ? 1.f : 0.f;
        a.w = (nib & 8u) ? 1.f : 0.f;
        if (nib & 15u) {
            int4 r4 = rnk4[q];
            tr.x = (nib & 1u) ? trow[r4.x] : 0.f;
            tr.y = (nib & 2u) ? trow[r4.y] : 0.f;
            tr.z = (nib & 4u) ? trow[r4.z] : 0.f;
            tr.w = (nib & 8u) ? trow[r4.w] : 0.f;
        } else {
            tr = make_float4(0.f, 0.f, 0.f, 0.f);
        }
        *(float4*)&out[baseA + 4u * q] = a;
        *(float4*)&out[baseT + 4u * q] = tr;
    }
}

// ---------------- launch ---------------------------------------------------
extern "C" void kernel_launch(void* const* d_in, const int* in_sizes, int n_in,
                              void* d_out, int out_size) {
    const float* residue    = (const float*)d_in[0];
    const float* constraint = (const float*)d_in[1];
    const float* eps        = (const float*)d_in[2];
    float* out = (float*)d_out;

    prep_kernel<<<512, 256>>>(residue, constraint, eps, out);   // launch 1
    ranks_kernel<<<1, 128>>>();                                 // launch 2
    nop_kernel<<<1, 32>>>();                                    // launch 3

    dim3 gGrid(32, 32);
    dist_kernel<<<gGrid, 256>>>(constraint);                    // launch 4 (ncu)

    hist0_kernel<<<2048, 256>>>();
    scan_kernel<<<1, 128>>>(0);
    hist12_kernel<1><<<2048, 256>>>();
    scan_kernel<<<1, 128>>>(1);
    hist12_kernel<2><<<2048, 256>>>();
    scan_kernel<<<1, 128>>>(2);

    bits_kernel<<<65536, 256>>>();

    dim3 cGrid(4096, NEPS);
    compact_kernel<<<cGrid, 128>>>();

    dim3 aGrid(32, NEPS);
    as8_kernel<<<aGrid, 256>>>();

    dim3 tGrid(32, 32, NEPS);
    tric_imma_kernel<<<tGrid, 256>>>();

    expand_kernel<<<cGrid, 256>>>(out);
}

// round 17
// speedup vs baseline: 1.2783x; 1.2783x over previous
#include <cuda_runtime.h>

// Problem constants
#define NPTS 4096
#define DIMK 256
#define NEPS 4
#define NWRD 128              // 4096 bits / 32 per row
#define NN   (NPTS*NPTS)      // 16777216

// Output layout (float32, concatenated in reference return order)
#define LOSS_OFF 0u
#define VM_OFF   4096u
#define A_OFF    20480u                      // 4096 + 4*4096
#define TRI_OFF  (20480u + 67108864u)        // + E*N*N

// ---------------- device scratch (globals: allocation-free rule) ----------
__device__ float          g_d[NN];                 // 67 MB distance matrix
__device__ unsigned       g_abits[NEPS][NPTS*NWRD];// 8 MB packed adjacency
__device__ unsigned       g_cbits[NEPS][NPTS*NWRD];// 8 MB compacted adjacency
__device__ float          g_tric[(size_t)NEPS*NN]; // 268 MB compacted counts
__device__ float          g_sq[NPTS];
__device__ unsigned char  g_vmb[NPTS];             // 4 mask bits per point
__device__ unsigned char  g_lvl[NPTS];             // first alive level (4=dead)
__device__ int            g_rank[NEPS][NPTS];      // rank among alive, -1 dead
__device__ int            g_plist[NEPS][NPTS];     // rank -> point index
__device__ int            g_m[NEPS];               // alive count
__device__ unsigned       g_hist[NEPS][2048];      // radix histograms (L or e)
__device__ unsigned       g_pref[NEPS];
__device__ unsigned       g_k[NEPS];
__device__ unsigned       g_thrbits[NEPS];
__device__ int            g_done[NEPS];

// ---------------- Stage 1: losses, vmask, sqnorms, levels -------------------
// Bit-exact XLA row-reduce: warp per row, lane-stride-32 ascending FMA, then
// shfl_down tree (16,8,4,2,1). DO NOT change the arithmetic order.
__global__ void prep_kernel(const float* __restrict__ residue,
                            const float* __restrict__ constraint,
                            const float* __restrict__ eps,
                            float* __restrict__ out) {
    int gw   = (blockIdx.x * blockDim.x + threadIdx.x) >> 5;   // row id
    int lane = threadIdx.x & 31;
    if (gw >= NPTS) return;

    const float* __restrict__ c = constraint + (unsigned)gw * DIMK;
    const float* __restrict__ r = residue    + (unsigned)gw * DIMK;

    float s_sq = 0.f, s_ls = 0.f;
    #pragma unroll
    for (int j = 0; j < 8; j++) {
        float cv = c[lane + 32 * j];
        float rv = r[lane + 32 * j];
        s_sq = __fmaf_rn(cv, cv, s_sq);
        float df = __fadd_rn(rv, -cv);
        s_ls = __fmaf_rn(df, df, s_ls);
    }
    #pragma unroll
    for (int o = 16; o > 0; o >>= 1) {
        s_sq = __fadd_rn(s_sq, __shfl_down_sync(0xffffffffu, s_sq, o));
        s_ls = __fadd_rn(s_ls, __shfl_down_sync(0xffffffffu, s_ls, o));
    }

    if (lane == 0) {
        g_sq[gw] = s_sq;
        float loss = __fsqrt_rn(s_ls);
        out[LOSS_OFF + gw] = loss;
        unsigned char mb = 0;
        #pragma unroll
        for (int e = 0; e < NEPS; e++) {
            bool m = loss <= eps[e];
            mb |= (unsigned char)((m ? 1 : 0) << e);
            out[VM_OFF + (unsigned)e * NPTS + gw] = m ? 1.f : 0.f;
        }
        g_vmb[gw] = mb;
        g_lvl[gw] = (unsigned char)(mb ? (__ffs((int)mb) - 1) : NEPS);
    }
}

// ---------------- Stage 1b: per-eps compaction ranks ------------------------
__global__ void ranks_kernel() {
    int e = threadIdx.x >> 5, lane = threadIdx.x & 31;
    int base = lane * 128;
    int cnt = 0;
    for (int q = 0; q < 128; q++)
        cnt += (g_vmb[base + q] >> e) & 1;
    int incl = cnt;
    #pragma unroll
    for (int o = 1; o < 32; o <<= 1) {
        int v = __shfl_up_sync(0xffffffffu, incl, o);
        if (lane >= o) incl += v;
    }
    int m = __shfl_sync(0xffffffffu, incl, 31);
    int run = incl - cnt;
    for (int q = 0; q < 128; q++) {
        int idx = base + q;
        if ((g_vmb[idx] >> e) & 1) {
            g_rank[e][idx] = run;
            g_plist[e][run] = idx;
            run++;
        } else {
            g_rank[e][idx] = -1;
        }
    }
    if (lane == 0) g_m[e] = m;
}

// ---------------- Stage 2: pairwise distances (fp32, packed FFMA2) ---------
// Round-11 j-packed config (best measured). Triangular grid; bit-exact
// symmetric mirror via smem-staged transpose. Single accumulator per element,
// k strictly ascending -> bit-exact.
__global__ void __launch_bounds__(256, 2)
dist_kernel(const float* __restrict__ C) {
    int bx = blockIdx.x, by = blockIdx.y;
    if (by > bx) return;

    __shared__ __align__(16) float smem[64 * 129];   // 33 KB union buffer
    float* shI = smem;                  // 16*132 floats
    float* shJ = smem + 16 * 132;       // 16*132 floats
    float* stage = smem;                // 64*129 floats (post-mainloop)

    int i0 = by * 128, j0 = bx * 128;
    int t  = threadIdx.x;
    int tx = t & 15, ty = t >> 4;
    unsigned long long accp[8][4] = {};   // (lo,hi) fp32 pairs, init 0.0f

    for (int k0 = 0; k0 < DIMK; k0 += 16) {
        #pragma unroll
        for (int r = 0; r < 2; r++) {
            int q   = t + r * 256;        // 0..511
            int row = q & 127;
            int kv  = q >> 7;             // 0..3 -> k offset kv*4
            float4 vI = *(const float4*)&C[(i0 + row) * DIMK + k0 + kv * 4];
            float4 vJ = *(const float4*)&C[(j0 + row) * DIMK + k0 + kv * 4];
            shI[(kv * 4 + 0) * 132 + row] = vI.x;
            shI[(kv * 4 + 1) * 132 + row] = vI.y;
            shI[(kv * 4 + 2) * 132 + row] = vI.z;
            shI[(kv * 4 + 3) * 132 + row] = vI.w;
            shJ[(kv * 4 + 0) * 132 + row] = vJ.x;
            shJ[(kv * 4 + 1) * 132 + row] = vJ.y;
            shJ[(kv * 4 + 2) * 132 + row] = vJ.z;
            shJ[(kv * 4 + 3) * 132 + row] = vJ.w;
        }
        __syncthreads();
        #pragma unroll
        for (int kk = 0; kk < 16; kk++) {
            unsigned long long aid[8], bjp[4];
            #pragma unroll
            for (int a = 0; a < 8; a++) {
                unsigned av = __float_as_uint(shI[kk * 132 + ty + 16 * a]);
                asm("mov.b64 %0, {%1, %1};" : "=l"(aid[a]) : "r"(av));
            }
            #pragma unroll
            for (int b = 0; b < 4; b++)
                bjp[b] = *(const unsigned long long*)
                             &shJ[kk * 132 + (tx + 16 * b) * 2];
            #pragma unroll
            for (int a = 0; a < 8; a++)
                #pragma unroll
                for (int b = 0; b < 4; b++)
                    asm("fma.rn.f32x2 %0, %1, %2, %3;"
                        : "=l"(accp[a][b])
                        : "l"(aid[a]), "l"(bjp[b]), "l"(accp[a][b]));
        }
        __syncthreads();
    }

    float sqi[8];
    #pragma unroll
    for (int a = 0; a < 8; a++) sqi[a] = g_sq[i0 + ty + 16 * a];

    #pragma unroll
    for (int h = 0; h < 2; h++) {
        __syncthreads();
        #pragma unroll
        for (int a4 = 0; a4 < 4; a4++) {
            int a  = h * 4 + a4;
            int il = ty + 16 * a;                   // local i row
            int i  = i0 + il;
            #pragma unroll
            for (int b = 0; b < 4; b++) {
                unsigned lo, hi;
                asm("mov.b64 {%0, %1}, %2;"
                    : "=r"(lo), "=r"(hi) : "l"(accp[a][b]));
                int jcl = (tx + 16 * b) * 2;        // local j col (even)
                int jc  = j0 + jcl;
                float accv[2] = {__uint_as_float(lo), __uint_as_float(hi)};
                float v[2];
                #pragma unroll
                for (int hh = 0; hh < 2; hh++) {
                    float t1 = __fadd_rn(sqi[a], g_sq[jc + hh]);
                    float g2 = __fmul_rn(2.0f, accv[hh]);
                    float d2 = __fadd_rn(t1, -g2);
                    v[hh] = __fsqrt_rn(fmaxf(d2, 0.0f));
                    stage[(il - h * 64) * 129 + jcl + hh] = v[hh];
                }
                *(float2*)&g_d[(unsigned)i * NPTS + jc] = make_float2(v[0], v[1]);
            }
        }
        __syncthreads();
        if (bx != by) {
            #pragma unroll
            for (int a2 = 0; a2 < 8; a2++) {
                int jl = ty + 16 * a2;
                #pragma unroll
                for (int b2 = 0; b2 < 4; b2++) {
                    int ic = tx + 16 * b2;          // 0..63
                    g_d[(unsigned)(j0 + jl) * NPTS + i0 + h * 64 + ic] =
                        stage[ic * 129 + jl];
                }
            }
        }
    }
}

// ---------------- Stage 3a: pass-0 histogram, upper triangle, branchless ---
__global__ void hist0_kernel() {
    __shared__ unsigned sh[NEPS * 2048];
    int tid = threadIdx.x;
    for (int q = tid; q < NEPS * 2048; q += 256) sh[q] = 0;
    __syncthreads();

    unsigned lane = (unsigned)(tid & 31);
    const float4* __restrict__ d4 = (const float4*)g_d;
    for (unsigned idx = blockIdx.x * 256u + tid; idx < (unsigned)(NN / 4);
         idx += gridDim.x * 256u) {
        unsigned i  = idx >> 10;
        unsigned j4 = (idx & 1023u) * 4u;
        if (__all_sync(0xffffffffu, j4 + 3u < i)) continue;  // warp-uniform skip
        float4 v = d4[idx];
        uchar4 lj = *(const uchar4*)&g_lvl[j4];
        unsigned li = (unsigned)g_lvl[i];
        float dv[4] = {v.x, v.y, v.z, v.w};
        unsigned lv[4] = {max(li, (unsigned)lj.x), max(li, (unsigned)lj.y),
                          max(li, (unsigned)lj.z), max(li, (unsigned)lj.w)};
        #pragma unroll
        for (int c = 0; c < 4; c++) {
            unsigned j = j4 + (unsigned)c;
            unsigned w = (j > i) ? 2u : ((j == i) ? 1u : 0u);
            bool valid = (w != 0u) && (dv[c] > 0.f) && (lv[c] < (unsigned)NEPS);
            unsigned key = valid
                ? (lv[c] * 2048u + (__float_as_uint(dv[c]) >> 20))
                : (0x80000000u | lane);
            unsigned wc_ = valid ? w : 0u;
            unsigned peers = __match_any_sync(0xffffffffu, key);
            unsigned b0 = __ballot_sync(0xffffffffu, wc_ & 1u);
            unsigned b1 = __ballot_sync(0xffffffffu, wc_ & 2u);
            if (valid && lane == (unsigned)(__ffs(peers) - 1)) {
                unsigned s = __popc(peers & b0) + 2u * __popc(peers & b1);
                atomicAdd(&sh[key], s);
            }
        }
    }
    __syncthreads();
    unsigned* gh = &g_hist[0][0];
    for (int q = tid; q < NEPS * 2048; q += 256) {
        unsigned v = sh[q];
        if (v) atomicAdd(&gh[q], v);
    }
}

// ---------------- Stage 3b: passes 1,2 — upper triangle, direct atomics ----
template<int PASS>
__global__ void hist12_kernel() {
    __shared__ unsigned sh[NEPS * 2048];
    int tid = threadIdx.x;
    for (int q = tid; q < NEPS * 2048; q += 256) sh[q] = 0;
    __syncthreads();

    unsigned pref[NEPS];
    #pragma unroll
    for (int e = 0; e < NEPS; e++) pref[e] = g_pref[e];

    const float4* __restrict__ d4 = (const float4*)g_d;
    for (unsigned idx = blockIdx.x * 256u + tid; idx < (unsigned)(NN / 4);
         idx += gridDim.x * 256u) {
        unsigned i  = idx >> 10;
        unsigned j4 = (idx & 1023u) * 4u;
        if (j4 + 3u < i) continue;               // per-lane ok: atomics only
        float4 v = d4[idx];
        uchar4 lj = *(const uchar4*)&g_lvl[j4];
        unsigned li = (unsigned)g_lvl[i];
        float dv[4] = {v.x, v.y, v.z, v.w};
        unsigned lv[4] = {max(li, (unsigned)lj.x), max(li, (unsigned)lj.y),
                          max(li, (unsigned)lj.z), max(li, (unsigned)lj.w)};
        #pragma unroll
        for (int c = 0; c < 4; c++) {
            unsigned j = j4 + (unsigned)c;
            unsigned w = (j > i) ? 2u : ((j == i) ? 1u : 0u);
            if (w == 0u || !(dv[c] > 0.f) || lv[c] >= (unsigned)NEPS) continue;
            unsigned bits = __float_as_uint(dv[c]);
            unsigned hd   = (PASS == 1) ? (bits >> 20) : (bits >> 9);
            unsigned bin  = (PASS == 1) ? ((bits >> 9) & 2047u) : (bits & 511u);
            #pragma unroll
            for (int e = 0; e < NEPS; e++)
                if (lv[c] <= (unsigned)e && hd == pref[e])
                    atomicAdd(&sh[e * 2048 + bin], w);
        }
    }
    __syncthreads();
    unsigned* gh = &g_hist[0][0];
    for (int q = tid; q < NEPS * 2048; q += 256) {
        unsigned v = sh[q];
        if (v) atomicAdd(&gh[q], v);
    }
}

__global__ void scan_kernel(int pass) {
    __shared__ unsigned shh[NEPS * 2048];
    int tid = threadIdx.x;              // 128 threads: warp e handles eps e
    int e = tid >> 5, lane = tid & 31;

    unsigned* gh = &g_hist[0][0];
    for (int q = tid; q < NEPS * 2048; q += 128) shh[q] = gh[q];
    __syncthreads();

    unsigned chunkSum = 0;
    for (int q = 0; q < 64; q++) {
        unsigned hv;
        if (pass == 0) {
            hv = 0;
            for (int L = 0; L <= e; L++) hv += shh[L * 2048 + lane * 64 + q];
        } else {
            hv = shh[e * 2048 + lane * 64 + q];
        }
        chunkSum += hv;
    }

    unsigned incl = chunkSum;
    #pragma unroll
    for (int o = 1; o < 32; o <<= 1) {
        unsigned v = __shfl_up_sync(0xffffffffu, incl, o);
        if (lane >= o) incl += v;
    }
    unsigned total = __shfl_sync(0xffffffffu, incl, 31);
    unsigned exclusive = incl - chunkSum;

    if (pass == 0 && lane == 0) {
        if (total == 0) {
            g_done[e] = 1;
            g_thrbits[e] = 0x7F800000u;   // +inf
            g_pref[e] = 0xFFFFFFFFu;      // impossible prefix
        } else {
            g_done[e] = 0;
        }
    }

    bool skip = (pass > 0) && (g_done[e] != 0);
    if (!skip && total > 0) {
        unsigned k = (pass == 0) ? ((total - 1u) >> 1) : g_k[e];
        bool mine = (exclusive <= k) && (k < exclusive + chunkSum);
        if (mine) {
            unsigned cum = exclusive, b = 0;
            for (int q = 0; q < 64; q++) {
                unsigned h;
                if (pass == 0) {
                    h = 0;
                    for (int L = 0; L <= e; L++) h += shh[L * 2048 + lane * 64 + q];
                } else {
                    h = shh[e * 2048 + lane * 64 + q];
                }
                if (cum + h > k) { b = (unsigned)(lane * 64 + q); break; }
                cum += h;
            }
            g_k[e] = k - cum;
            if (pass == 0)      g_pref[e] = b;
            else if (pass == 1) g_pref[e] = (g_pref[e] << 11) | b;
            else                g_thrbits[e] = (g_pref[e] << 9) | b;
        }
    }
    __syncthreads();
    for (int q = tid; q < NEPS * 2048; q += 128) gh[q] = 0;
}

// ---------------- Stage 4: fused adjacency bits + rank compaction -----------
// One block per row i (128 threads). Warp w covers words wc = w+4q, so each
// warp iteration reads 128 consecutive bytes of g_d (coalesced). Row bits are
// kept in smem for the compaction phase (no g_abits re-read, one launch).
__global__ void bitscompact_kernel() {
    int i = blockIdx.x;
    int t = threadIdx.x, w = t >> 5, lane = t & 31;
    __shared__ unsigned rb[NEPS][128];

    float thr[NEPS];
    #pragma unroll
    for (int e = 0; e < NEPS; e++) thr[e] = __uint_as_float(g_thrbits[e]);
    unsigned mi = (unsigned)g_vmb[i];

    for (int q = 0; q < 32; q++) {
        int wc = w + q * 4;              // 0..127
        int j  = wc * 32 + lane;
        float dv = g_d[(unsigned)i * NPTS + j];
        unsigned both = mi & (unsigned)g_vmb[j];
        bool offd = (i != j);
        #pragma unroll
        for (int e = 0; e < NEPS; e++) {
            bool a = (dv <= thr[e]) && ((both >> e) & 1u) && offd;
            unsigned word = __ballot_sync(0xffffffffu, a);
            if (lane == 0) {
                rb[e][wc] = word;
                g_abits[e][(unsigned)i * NWRD + wc] = word;
            }
        }
    }
    __syncthreads();

    #pragma unroll
    for (int e = 0; e < NEPS; e++) {
        int rk = g_rank[e][i];
        if (rk < 0) continue;
        int m = g_m[e];
        const int* __restrict__ pl = g_plist[e];
        unsigned wd = 0;
        int base = t * 32;
        for (int b = 0; b < 32; b++) {
            int idx = base + b;
            if (idx < m) {
                int p = pl[idx];
                wd |= ((rb[e][p >> 5] >> (p & 31)) & 1u) << b;
            }
        }
        g_cbits[e][rk * 128 + t] = wd;
    }
}

// ---------------- Stage 5: compacted (A@A) via bitset popcount --------------
// r11 structure; inner loop re-shaped to minimize live registers (bj[8] per
// w2, single ai at a time) to avoid the 128-reg cap / spills.
__global__ void __launch_bounds__(256, 2)
tric_kernel() {
    int bx = blockIdx.x, by = blockIdx.y, e = blockIdx.z;
    int m = g_m[e];
    int nt = (m + 127) >> 7;
    if (bx >= nt || by > bx) return;
    int kch = (m + 1023) >> 10;          // 32-word chunks actually occupied
    int i0 = by * 128, j0 = bx * 128;

    __shared__ __align__(16) unsigned char smraw[128 * 34 * 4 * 2]; // 34816 B
    unsigned* shI = (unsigned*)smraw;
    unsigned* shJ = shI + 128 * 34;
    float* stage  = (float*)smraw;       // 64*129 floats, reused after compute

    int t  = threadIdx.x;
    int tx = t & 15, ty = t >> 4;
    int acc[8][8] = {};
    const unsigned* __restrict__ Ab = g_cbits[e];
    float* __restrict__ trc = g_tric + (size_t)e * NN;

    for (int kc = 0; kc < kch; kc++) {
        #pragma unroll
        for (int r = 0; r < 16; r++) {
            int q = t + r * 256;              // 0..4095
            int row = q >> 5, w = q & 31;
            shI[row * 34 + w] = Ab[(i0 + row) * NWRD + kc * 32 + w];
        }
        #pragma unroll
        for (int r = 0; r < 16; r++) {
            int q = t + r * 256;
            int row = q >> 5, w = q & 31;
            shJ[row * 34 + w] = Ab[(j0 + row) * NWRD + kc * 32 + w];
        }
        __syncthreads();

        #pragma unroll 4
        for (int w2 = 0; w2 < 16; w2++) {
            uint2 bj[8];
            #pragma unroll
            for (int b = 0; b < 8; b++)
                bj[b] = *(const uint2*)&shJ[(tx + 16 * b) * 34 + 2 * w2];
            #pragma unroll
            for (int a = 0; a < 8; a++) {
                uint2 ai = *(const uint2*)&shI[(ty + 16 * a) * 34 + 2 * w2];
                #pragma unroll
                for (int b = 0; b < 8; b++)
                    acc[a][b] += __popc(ai.x & bj[b].x)
                               + __popc(ai.y & bj[b].y);
            }
        }
        __syncthreads();
    }

    #pragma unroll
    for (int a = 0; a < 8; a++) {
        int il = ty + 16 * a;
        #pragma unroll
        for (int b = 0; b < 8; b++) {
            int jc = tx + 16 * b;
            trc[(unsigned)(i0 + il) * 4096u + j0 + jc] = (float)acc[a][b];
        }
    }

    if (bx != by) {
        #pragma unroll
        for (int h = 0; h < 2; h++) {
            __syncthreads();
            #pragma unroll
            for (int a = h * 4; a < h * 4 + 4; a++) {
                int il = ty + 16 * a;
                int i64 = il - h * 64;               // 0..63
                #pragma unroll
                for (int b = 0; b < 8; b++) {
                    int jc = tx + 16 * b;
                    stage[i64 * 129 + jc] = (float)acc[a][b];
                }
            }
            __syncthreads();
            #pragma unroll
            for (int a = 0; a < 8; a++) {
                int jl = ty + 16 * a;                // output row within j-tile
                #pragma unroll
                for (int b = 0; b < 4; b++) {
                    int ic = tx + 16 * b;            // 0..63
                    trc[(unsigned)(j0 + jl) * 4096u + i0 + h * 64 + ic] =
                        stage[ic * 129 + jl];
                }
            }
        }
    }
}

// ---------------- Stage 6: expand A and tri to full output ------------------
__global__ void expand_kernel(float* __restrict__ out) {
    int i = blockIdx.x, e = blockIdx.y;
    unsigned baseA = A_OFF   + (unsigned)e * 16777216u + (unsigned)i * 4096u;
    unsigned baseT = TRI_OFF + (unsigned)e * 16777216u + (unsigned)i * 4096u;
    int t = threadIdx.x;                 // 256 threads
    int mi = g_rank[e][i];

    if (mi < 0) {
        float4 z = make_float4(0.f, 0.f, 0.f, 0.f);
        #pragma unroll
        for (int q = t; q < 1024; q += 256) {
            *(float4*)&out[baseA + 4u * q] = z;
            *(float4*)&out[baseT + 4u * q] = z;
        }
        return;
    }

    __shared__ unsigned rowbits[128];
    if (t < 128) rowbits[t] = g_abits[e][i * 128 + t];
    __syncthreads();

    const float* __restrict__ trow = g_tric + (size_t)e * NN + (size_t)mi * 4096u;
    const int4* __restrict__ rnk4 = (const int4*)g_rank[e];

    #pragma unroll
    for (int q = t; q < 1024; q += 256) {
        unsigned nib = rowbits[q >> 3] >> ((q & 7) * 4);   // 4 bits for j=4q..
        float4 a, tr;
        a.x = (nib & 1u) ? 1.f : 0.f;
        a.y = (nib & 2u) ? 1.f : 0.f;
        a.z = (nib & 4u) ? 1.f : 0.f;
        a.w = (nib & 8u) ? 1.f : 0.f;
        if (nib & 15u) {
            int4 r4 = rnk4[q];
            tr.x = (nib & 1u) ? trow[r4.x] : 0.f;
            tr.y = (nib & 2u) ? trow[r4.y] : 0.f;
            tr.z = (nib & 4u) ? trow[r4.z] : 0.f;
            tr.w = (nib & 8u) ? trow[r4.w] : 0.f;
        } else {
            tr = make_float4(0.f, 0.f, 0.f, 0.f);
        }
        *(float4*)&out[baseA + 4u * q] = a;
        *(float4*)&out[baseT + 4u * q] = tr;
    }
}

// ---------------- launch ---------------------------------------------------
extern "C" void kernel_launch(void* const* d_in, const int* in_sizes, int n_in,
                              void* d_out, int out_size) {
    const float* residue    = (const float*)d_in[0];
    const float* constraint = (const float*)d_in[1];
    const float* eps        = (const float*)d_in[2];
    float* out = (float*)d_out;

    prep_kernel<<<512, 256>>>(residue, constraint, eps, out);   // launch 1
    ranks_kernel<<<1, 128>>>();                                 // launch 2

    dim3 gGrid(32, 32);
    dist_kernel<<<gGrid, 256>>>(constraint);                    // launch 3

    hist0_kernel<<<2048, 256>>>();                              // launch 4 (ncu)
    scan_kernel<<<1, 128>>>(0);
    hist12_kernel<1><<<2048, 256>>>();
    scan_kernel<<<1, 128>>>(1);
    hist12_kernel<2><<<2048, 256>>>();
    scan_kernel<<<1, 128>>>(2);

    bitscompact_kernel<<<4096, 128>>>();

    dim3 tGrid(32, 32, NEPS);
    tric_kernel<<<tGrid, 256>>>();

    dim3 cGrid(4096, NEPS);
    expand_kernel<<<cGrid, 256>>>(out);
}